// round 10
// baseline (speedup 1.0000x reference)
#include <cuda_runtime.h>
#include <cuda_bf16.h>
#include <cstdint>
#include <math.h>

// Problem: B=64, S=1024, I=256, H=256, G=3H=768, two GRU layers.
#define PB 64
#define PS 1024
#define PH 256
#define PG 768
#define BSH (PB * PS * PH)   // 16,777,216

typedef unsigned long long ull;

// Scratch (device globals: the sanctioned no-alloc workaround)
__device__ float g_xg[(size_t)PB * PS * PG];  // per-layer input projections [B,S,768]
__device__ float g_h1[(size_t)PB * PS * PH];  // layer-0 hidden states [B,S,256]

// ---- f32x2 packed helpers (PTX-only path; ptxas won't emit FFMA2 from C++) ----
__device__ __forceinline__ void fma2(ull& d, ull a, ull b) {
    asm("fma.rn.f32x2 %0, %1, %2, %0;" : "+l"(d) : "l"(a), "l"(b));
}
__device__ __forceinline__ ull dup2(float x) {
    ull r;
    asm("mov.b64 %0, {%1, %1};" : "=l"(r) : "f"(x));
    return r;
}
__device__ __forceinline__ ull pack2(float lo, float hi) {
    ull r;
    asm("mov.b64 %0, {%1, %2};" : "=l"(r) : "f"(lo), "f"(hi));
    return r;
}
__device__ __forceinline__ float2 unpack2(ull v) {
    float lo, hi;
    asm("mov.b64 {%0, %1}, %2;" : "=f"(lo), "=f"(hi) : "l"(v));
    return make_float2(lo, hi);
}
__device__ __forceinline__ uint32_t smem_u32(const void* p) {
    uint32_t a;
    asm("{ .reg .u64 t; cvta.to.shared.u64 t, %1; cvt.u32.u64 %0, t; }"
        : "=r"(a) : "l"(p));
    return a;
}
__device__ __forceinline__ float tanh_ap(float x) {
    float y;
    asm("tanh.approx.f32 %0, %1;" : "=f"(y) : "f"(x));
    return y;
}

// ---------------------------------------------------------------------------
// GEMM: out[m][n] = sum_k A[m][k] * W[n][k] + bias[n]
// A: [65536][256], W: [768][256], out: [65536][768]
// BM=128, BN=64, BK=32, 256 threads, 8x4 per thread, row-pair f32x2 accum.
// ---------------------------------------------------------------------------
__global__ __launch_bounds__(256) void gemm_xg(
    const float* __restrict__ A, const float* __restrict__ W,
    const float* __restrict__ bias, float* __restrict__ out)
{
    __shared__ __align__(16) float Xs[32][132];  // [k][m] transposed, padded
    __shared__ __align__(16) float Ws[32][68];   // [k][n] transposed, padded

    const int t  = threadIdx.x;
    const int bn = blockIdx.x;   // 0..11
    const int bm = blockIdx.y;   // 0..511
    const int tx = t & 15;       // n-group (4 cols)
    const int ty = t >> 4;       // m-group (8 rows = 4 row-pairs)

    const float* Ablk = A + (size_t)bm * 128 * 256;
    const float* Wblk = W + (size_t)bn * 64 * 256;

    ull acc[4][4];  // [row-pair][col], f32x2 packed (row2p, row2p+1)
#pragma unroll
    for (int i = 0; i < 4; i++)
#pragma unroll
        for (int j = 0; j < 4; j++) acc[i][j] = 0ull;

    const int a_row = t >> 3;  // 0..31
    const int a_kc  = t & 7;   // 0..7 (float4 along K)

    for (int kt = 0; kt < 256; kt += 32) {
#pragma unroll
        for (int r = 0; r < 4; r++) {
            int row = a_row + r * 32;
            float4 v = *reinterpret_cast<const float4*>(Ablk + (size_t)row * 256 + kt + a_kc * 4);
            Xs[a_kc * 4 + 0][row] = v.x;
            Xs[a_kc * 4 + 1][row] = v.y;
            Xs[a_kc * 4 + 2][row] = v.z;
            Xs[a_kc * 4 + 3][row] = v.w;
        }
#pragma unroll
        for (int r = 0; r < 2; r++) {
            int row = a_row + r * 32;
            float4 v = *reinterpret_cast<const float4*>(Wblk + (size_t)row * 256 + kt + a_kc * 4);
            Ws[a_kc * 4 + 0][row] = v.x;
            Ws[a_kc * 4 + 1][row] = v.y;
            Ws[a_kc * 4 + 2][row] = v.z;
            Ws[a_kc * 4 + 3][row] = v.w;
        }
        __syncthreads();

#pragma unroll
        for (int kk = 0; kk < 32; kk++) {
            ull a01 = *reinterpret_cast<const ull*>(&Xs[kk][ty * 8 + 0]);
            ull a23 = *reinterpret_cast<const ull*>(&Xs[kk][ty * 8 + 2]);
            ull a45 = *reinterpret_cast<const ull*>(&Xs[kk][ty * 8 + 4]);
            ull a67 = *reinterpret_cast<const ull*>(&Xs[kk][ty * 8 + 6]);
            float4 b4 = *reinterpret_cast<const float4*>(&Ws[kk][tx * 4]);
            ull b0 = dup2(b4.x), b1 = dup2(b4.y), b2 = dup2(b4.z), b3 = dup2(b4.w);
            fma2(acc[0][0], a01, b0); fma2(acc[0][1], a01, b1); fma2(acc[0][2], a01, b2); fma2(acc[0][3], a01, b3);
            fma2(acc[1][0], a23, b0); fma2(acc[1][1], a23, b1); fma2(acc[1][2], a23, b2); fma2(acc[1][3], a23, b3);
            fma2(acc[2][0], a45, b0); fma2(acc[2][1], a45, b1); fma2(acc[2][2], a45, b2); fma2(acc[2][3], a45, b3);
            fma2(acc[3][0], a67, b0); fma2(acc[3][1], a67, b1); fma2(acc[3][2], a67, b2); fma2(acc[3][3], a67, b3);
        }
        __syncthreads();
    }

    float4 bv = *reinterpret_cast<const float4*>(bias + bn * 64 + tx * 4);
#pragma unroll
    for (int i = 0; i < 4; i++) {
        float2 c0 = unpack2(acc[i][0]);
        float2 c1 = unpack2(acc[i][1]);
        float2 c2 = unpack2(acc[i][2]);
        float2 c3 = unpack2(acc[i][3]);
        size_t m0 = (size_t)bm * 128 + ty * 8 + 2 * i;
        float4 o0, o1;
        o0.x = c0.x + bv.x; o0.y = c1.x + bv.y; o0.z = c2.x + bv.z; o0.w = c3.x + bv.w;
        o1.x = c0.y + bv.x; o1.y = c1.y + bv.y; o1.z = c2.y + bv.z; o1.w = c3.y + bv.w;
        *reinterpret_cast<float4*>(out + m0 * 768 + bn * 64 + tx * 4) = o0;
        *reinterpret_cast<float4*>(out + (m0 + 1) * 768 + bn * 64 + tx * 4) = o1;
    }
}

// ---------------------------------------------------------------------------
// GRU recurrence: cluster of 4 CTAs handles 2 batches. CTA rank r owns hidden
// indices [64r, 64r+64) => W_hh rows {g*256 + 64r + j}. The 192x256 W slice
// lives in REGISTERS (row-pair f32x2 packed: 96 b64/thread). h is kept in SMEM
// PRE-DUPLICATED as (h,h) b64 pairs so the matvec feeds fma2 straight from
// LDS.128 broadcasts (no dup movs). Double-buffered; exchanged between the 4
// cluster CTAs via DSMEM b64 stores + barrier.cluster per step.
// Thread (kh = t>>5, lane = t&31): rows 6*lane..6*lane+5, k in [32*kh, 32*kh+32).
// ---------------------------------------------------------------------------
__global__ void __launch_bounds__(256, 1) __cluster_dims__(4, 1, 1)
gru_rec(const float* __restrict__ xg, const float* __restrict__ Whh,
        const float* __restrict__ bhh,
        float* __restrict__ dA, long long sA, int oA,
        float* __restrict__ dB, long long sB, int oB)
{
    __shared__ __align__(16) ull sh2[1024];    // [2 dbuf][2 batch][256] (h,h) pairs
    __shared__ __align__(16) float pr[3072];   // [8 kh][2 batch][192 rows]

    const int t    = threadIdx.x;
    const int rank = blockIdx.x & 3;
    const int pair = blockIdx.x >> 2;   // 0..31
    const int kh   = t >> 5;            // k-chunk 0..7
    const int lane = t & 31;            // row-group (6 rows each)

    // --- Load W_hh slice into registers, row-pair packed ---
    ull w[3][32];
#pragma unroll
    for (int pch = 0; pch < 3; pch++) {
        int ra = 6 * lane + 2 * pch;
        int rb_ = ra + 1;
        const float* s0 = Whh + (size_t)(((ra  >> 6) << 8) + (rank << 6) + (ra  & 63)) * 256 + kh * 32;
        const float* s1 = Whh + (size_t)(((rb_ >> 6) << 8) + (rank << 6) + (rb_ & 63)) * 256 + kh * 32;
#pragma unroll
        for (int kk = 0; kk < 32; kk++)
            w[pch][kk] = pack2(s0[kk], s1[kk]);
    }

    for (int i = t; i < 1024; i += 256) sh2[i] = 0ull;  // h0 = 0 (both buffers)
    __syncthreads();

    // epilogue role (t < 128)
    const int rb = t >> 6;
    const int rj = t & 63;
    const int jg = (rank << 6) + rj;
    const long long bG_r = (long long)pair * 2 + rb;
    float bh0 = 0.f, bh1 = 0.f, bh2 = 0.f;
    const float* xp_base = xg;
    if (t < 128) {
        bh0 = bhh[jg];
        bh1 = bhh[256 + jg];
        bh2 = bhh[512 + jg];
        xp_base = xg + (bG_r << 10) * 768;
    }

    const uint32_t shbase = smem_u32(sh2);
    float2* const pp = reinterpret_cast<float2*>(pr + kh * 384 + 6 * lane);

    for (int s = 0; s < PS; s++) {
        const int cur = s & 1, nxt = cur ^ 1;

        // prefetch xg + previous-h (consumed after syncthreads)
        float xr = 0.f, xz = 0.f, xn = 0.f, hp = 0.f;
        if (t < 128) {
            const float* xp = xp_base + (size_t)s * 768;
            xr = xp[jg];
            xz = xp[256 + jg];
            xn = xp[512 + jg];
            hp = reinterpret_cast<const float*>(&sh2[(cur * 2 + rb) * 256 + jg])[0];
        }

        // --- matvec: both batches, weights from regs, duplicated-h LDS.128 ---
#pragma unroll
        for (int b = 0; b < 2; b++) {
            ull a0 = 0ull, a1 = 0ull, a2 = 0ull;
            const ulonglong2* h2v =
                reinterpret_cast<const ulonglong2*>(sh2 + (cur * 2 + b) * 256 + kh * 32);
#pragma unroll
            for (int k2 = 0; k2 < 16; k2++) {
                ulonglong2 hq = h2v[k2];
                fma2(a0, w[0][2 * k2 + 0], hq.x);
                fma2(a1, w[1][2 * k2 + 0], hq.x);
                fma2(a2, w[2][2 * k2 + 0], hq.x);
                fma2(a0, w[0][2 * k2 + 1], hq.y);
                fma2(a1, w[1][2 * k2 + 1], hq.y);
                fma2(a2, w[2][2 * k2 + 1], hq.y);
            }
            float2* pb = pp + b * 96;   // +192 floats
            pb[0] = unpack2(a0);
            pb[1] = unpack2(a1);
            pb[2] = unpack2(a2);
        }
        __syncthreads();

        // --- reduce + gates + broadcast h_new to all 4 cluster CTAs ---
        if (t < 128) {
            float h0 = bh0, h1 = bh1, h2 = bh2;
#pragma unroll
            for (int q = 0; q < 8; q++) {
                const float* pq = pr + (q * 2 + rb) * 192;
                h0 += pq[rj];
                h1 += pq[64 + rj];
                h2 += pq[128 + rj];
            }
            // sigmoid(x) = 0.5 + 0.5*tanh(x/2); tanh via MUFU approx
            float r = 0.5f + 0.5f * tanh_ap(0.5f * (xr + h0));
            float z = 0.5f + 0.5f * tanh_ap(0.5f * (xz + h1));
            float n = tanh_ap(xn + r * h2);
            float hn = (1.f - z) * n + z * hp;

            ull hnp = pack2(hn, hn);
            uint32_t la = shbase + (uint32_t)(((nxt * 2 + rb) * 256 + jg) * 8);
#pragma unroll
            for (int rr = 0; rr < 4; rr++) {
                asm volatile(
                    "{\n\t.reg .b32 ra;\n\t"
                    "mapa.shared::cluster.u32 ra, %0, %1;\n\t"
                    "st.shared::cluster.u64 [ra], %2;\n\t}"
                    :: "r"(la), "r"(rr), "l"(hnp) : "memory");
            }
            long long row = (bG_r << 10) + s;
            dA[row * sA + oA + jg] = hn;
            dB[row * sB + oB + jg] = hn;
        }
        asm volatile("barrier.cluster.arrive.aligned;" ::: "memory");
        asm volatile("barrier.cluster.wait.aligned;" ::: "memory");
    }
}

// ---------------------------------------------------------------------------
extern "C" void kernel_launch(void* const* d_in, const int* in_sizes, int n_in,
                              void* d_out, int out_size) {
    const float* inp   = (const float*)d_in[0];
    const float* W_ih0 = (const float*)d_in[1];
    const float* W_hh0 = (const float*)d_in[2];
    const float* b_ih0 = (const float*)d_in[3];
    const float* b_hh0 = (const float*)d_in[4];
    const float* W_ih1 = (const float*)d_in[5];
    const float* W_hh1 = (const float*)d_in[6];
    const float* b_ih1 = (const float*)d_in[7];
    const float* b_hh1 = (const float*)d_in[8];
    float* out = (float*)d_out;

    float *xgp = nullptr, *h1p = nullptr;
    cudaGetSymbolAddress((void**)&xgp, g_xg);
    cudaGetSymbolAddress((void**)&h1p, g_h1);

    dim3 ggrid(12, 512);

    // Layer 0
    gemm_xg<<<ggrid, 256>>>(inp, W_ih0, b_ih0, xgp);
    gru_rec<<<128, 256>>>(xgp, W_hh0, b_hh0,
                          h1p, 256, 0,
                          out + BSH, 512, 0);
    // Layer 1
    gemm_xg<<<ggrid, 256>>>(h1p, W_ih1, b_ih1, xgp);
    gru_rec<<<128, 256>>>(xgp, W_hh1, b_hh1,
                          out, 256, 0,
                          out + BSH, 512, 256);
}

// round 11
// speedup vs baseline: 1.4218x; 1.4218x over previous
#include <cuda_runtime.h>
#include <cuda_bf16.h>
#include <cstdint>
#include <math.h>

// Problem: B=64, S=1024, I=256, H=256, G=3H=768, two GRU layers.
#define PB 64
#define PS 1024
#define PH 256
#define PG 768
#define BSH (PB * PS * PH)   // 16,777,216

typedef unsigned long long ull;

// Scratch (device globals: the sanctioned no-alloc workaround)
__device__ float g_xg[(size_t)PB * PS * PG];  // per-layer input projections [B,S,768]
__device__ float g_h1[(size_t)PB * PS * PH];  // layer-0 hidden states [B,S,256]

// ---- f32x2 packed helpers (PTX-only path; ptxas won't emit FFMA2 from C++) ----
__device__ __forceinline__ void fma2(ull& d, ull a, ull b) {
    asm("fma.rn.f32x2 %0, %1, %2, %0;" : "+l"(d) : "l"(a), "l"(b));
}
__device__ __forceinline__ ull dup2(float x) {
    ull r;
    asm("mov.b64 %0, {%1, %1};" : "=l"(r) : "f"(x));
    return r;
}
__device__ __forceinline__ ull pack2(float lo, float hi) {
    ull r;
    asm("mov.b64 %0, {%1, %2};" : "=l"(r) : "f"(lo), "f"(hi));
    return r;
}
__device__ __forceinline__ float2 unpack2(ull v) {
    float lo, hi;
    asm("mov.b64 {%0, %1}, %2;" : "=f"(lo), "=f"(hi) : "l"(v));
    return make_float2(lo, hi);
}
__device__ __forceinline__ uint32_t smem_u32(const void* p) {
    uint32_t a;
    asm("{ .reg .u64 t; cvta.to.shared.u64 t, %1; cvt.u32.u64 %0, t; }"
        : "=r"(a) : "l"(p));
    return a;
}
__device__ __forceinline__ float tanh_ap(float x) {
    float y;
    asm("tanh.approx.f32 %0, %1;" : "=f"(y) : "f"(x));
    return y;
}
// Scalar DSMEM store with transaction-count completion at the TARGET CTA's mbarrier.
__device__ __forceinline__ void st_async_f32(uint32_t laddr, uint32_t lmbar,
                                             uint32_t rank, float v) {
    asm volatile(
        "{\n\t.reg .b32 ra, rm;\n\t"
        "mapa.shared::cluster.u32 ra, %0, %2;\n\t"
        "mapa.shared::cluster.u32 rm, %1, %2;\n\t"
        "st.async.shared::cluster.mbarrier::complete_tx::bytes.u32 [ra], %3, [rm];\n\t}"
        :: "r"(laddr), "r"(lmbar), "r"(rank), "r"(__float_as_uint(v)) : "memory");
}
__device__ __forceinline__ void mb_wait(uint32_t mbar, uint32_t phase) {
    uint32_t done;
    asm volatile(
        "{\n\t.reg .pred p;\n\t"
        "mbarrier.try_wait.parity.acquire.cluster.shared::cta.b64 p, [%1], %2, 0x989680;\n\t"
        "selp.b32 %0, 1, 0, p;\n\t}"
        : "=r"(done) : "r"(mbar), "r"(phase) : "memory");
    while (!done) {
        asm volatile(
            "{\n\t.reg .pred p;\n\t"
            "mbarrier.try_wait.parity.acquire.cluster.shared::cta.b64 p, [%1], %2, 0x989680;\n\t"
            "selp.b32 %0, 1, 0, p;\n\t}"
            : "=r"(done) : "r"(mbar), "r"(phase) : "memory");
    }
}

// ---------------------------------------------------------------------------
// GEMM: out[m][n] = sum_k A[m][k] * W[n][k] + bias[n]   (unchanged from R9)
// ---------------------------------------------------------------------------
__global__ __launch_bounds__(256) void gemm_xg(
    const float* __restrict__ A, const float* __restrict__ W,
    const float* __restrict__ bias, float* __restrict__ out)
{
    __shared__ __align__(16) float Xs[32][132];
    __shared__ __align__(16) float Ws[32][68];

    const int t  = threadIdx.x;
    const int bn = blockIdx.x;
    const int bm = blockIdx.y;
    const int tx = t & 15;
    const int ty = t >> 4;

    const float* Ablk = A + (size_t)bm * 128 * 256;
    const float* Wblk = W + (size_t)bn * 64 * 256;

    ull acc[4][4];
#pragma unroll
    for (int i = 0; i < 4; i++)
#pragma unroll
        for (int j = 0; j < 4; j++) acc[i][j] = 0ull;

    const int a_row = t >> 3;
    const int a_kc  = t & 7;

    for (int kt = 0; kt < 256; kt += 32) {
#pragma unroll
        for (int r = 0; r < 4; r++) {
            int row = a_row + r * 32;
            float4 v = *reinterpret_cast<const float4*>(Ablk + (size_t)row * 256 + kt + a_kc * 4);
            Xs[a_kc * 4 + 0][row] = v.x;
            Xs[a_kc * 4 + 1][row] = v.y;
            Xs[a_kc * 4 + 2][row] = v.z;
            Xs[a_kc * 4 + 3][row] = v.w;
        }
#pragma unroll
        for (int r = 0; r < 2; r++) {
            int row = a_row + r * 32;
            float4 v = *reinterpret_cast<const float4*>(Wblk + (size_t)row * 256 + kt + a_kc * 4);
            Ws[a_kc * 4 + 0][row] = v.x;
            Ws[a_kc * 4 + 1][row] = v.y;
            Ws[a_kc * 4 + 2][row] = v.z;
            Ws[a_kc * 4 + 3][row] = v.w;
        }
        __syncthreads();

#pragma unroll
        for (int kk = 0; kk < 32; kk++) {
            ull a01 = *reinterpret_cast<const ull*>(&Xs[kk][ty * 8 + 0]);
            ull a23 = *reinterpret_cast<const ull*>(&Xs[kk][ty * 8 + 2]);
            ull a45 = *reinterpret_cast<const ull*>(&Xs[kk][ty * 8 + 4]);
            ull a67 = *reinterpret_cast<const ull*>(&Xs[kk][ty * 8 + 6]);
            float4 b4 = *reinterpret_cast<const float4*>(&Ws[kk][tx * 4]);
            ull b0 = dup2(b4.x), b1 = dup2(b4.y), b2 = dup2(b4.z), b3 = dup2(b4.w);
            fma2(acc[0][0], a01, b0); fma2(acc[0][1], a01, b1); fma2(acc[0][2], a01, b2); fma2(acc[0][3], a01, b3);
            fma2(acc[1][0], a23, b0); fma2(acc[1][1], a23, b1); fma2(acc[1][2], a23, b2); fma2(acc[1][3], a23, b3);
            fma2(acc[2][0], a45, b0); fma2(acc[2][1], a45, b1); fma2(acc[2][2], a45, b2); fma2(acc[2][3], a45, b3);
            fma2(acc[3][0], a67, b0); fma2(acc[3][1], a67, b1); fma2(acc[3][2], a67, b2); fma2(acc[3][3], a67, b3);
        }
        __syncthreads();
    }

    float4 bv = *reinterpret_cast<const float4*>(bias + bn * 64 + tx * 4);
#pragma unroll
    for (int i = 0; i < 4; i++) {
        float2 c0 = unpack2(acc[i][0]);
        float2 c1 = unpack2(acc[i][1]);
        float2 c2 = unpack2(acc[i][2]);
        float2 c3 = unpack2(acc[i][3]);
        size_t m0 = (size_t)bm * 128 + ty * 8 + 2 * i;
        float4 o0, o1;
        o0.x = c0.x + bv.x; o0.y = c1.x + bv.y; o0.z = c2.x + bv.z; o0.w = c3.x + bv.w;
        o1.x = c0.y + bv.x; o1.y = c1.y + bv.y; o1.z = c2.y + bv.z; o1.w = c3.y + bv.w;
        *reinterpret_cast<float4*>(out + m0 * 768 + bn * 64 + tx * 4) = o0;
        *reinterpret_cast<float4*>(out + (m0 + 1) * 768 + bn * 64 + tx * 4) = o1;
    }
}

// ---------------------------------------------------------------------------
// GRU recurrence with split-phase mbarrier h-exchange (no barrier.cluster in
// the steady-state loop). W_hh slice in registers (R9 layout), h as plain f32
// (R10 pre-duplication reverted), tanh.approx gates.
// Exchange e (=h(e) bytes, e>=1) is guarded by mb[e&1] with expect_tx=2048
// (4 ranks x 128 f32). Producer is at most 1 step ahead of the slowest
// consumer, so re-arming mb[s&1] for exchange s+2 right after consuming
// exchange s is race-free.
// ---------------------------------------------------------------------------
#define EXG_BYTES 2048

__global__ void __launch_bounds__(256, 1) __cluster_dims__(4, 1, 1)
gru_rec(const float* __restrict__ xg, const float* __restrict__ Whh,
        const float* __restrict__ bhh,
        float* __restrict__ dA, long long sA, int oA,
        float* __restrict__ dB, long long sB, int oB)
{
    __shared__ __align__(16) float sh[1024];   // [2 dbuf][2 batch][256]
    __shared__ __align__(16) float pr[3072];   // [8 kh][2 batch][192 rows]
    __shared__ __align__(8)  ull  mbx[2];      // per-buffer exchange mbarriers

    const int t    = threadIdx.x;
    const int rank = blockIdx.x & 3;
    const int pair = blockIdx.x >> 2;   // 0..31
    const int kh   = t >> 5;            // k-chunk 0..7
    const int lane = t & 31;            // row-group (6 rows each)

    const uint32_t mb0 = smem_u32(&mbx[0]);
    const uint32_t mb1 = smem_u32(&mbx[1]);
    const uint32_t shbase = smem_u32(sh);

    // --- Load W_hh slice into registers, row-pair packed ---
    ull w[3][32];
#pragma unroll
    for (int pch = 0; pch < 3; pch++) {
        int ra = 6 * lane + 2 * pch;
        int rb_ = ra + 1;
        const float* s0 = Whh + (size_t)(((ra  >> 6) << 8) + (rank << 6) + (ra  & 63)) * 256 + kh * 32;
        const float* s1 = Whh + (size_t)(((rb_ >> 6) << 8) + (rank << 6) + (rb_ & 63)) * 256 + kh * 32;
#pragma unroll
        for (int kk = 0; kk < 32; kk++)
            w[pch][kk] = pack2(s0[kk], s1[kk]);
    }

    for (int i = t; i < 1024; i += 256) sh[i] = 0.f;  // h0 = 0 (both buffers)
    if (t == 0) {
        asm volatile("mbarrier.init.shared.b64 [%0], 1;" :: "r"(mb0) : "memory");
        asm volatile("mbarrier.init.shared.b64 [%0], 1;" :: "r"(mb1) : "memory");
        // Arm exchange 1 (mb1) and exchange 2 (mb0).
        asm volatile("mbarrier.arrive.expect_tx.shared.b64 _, [%0], %1;"
                     :: "r"(mb1), "r"(EXG_BYTES) : "memory");
        asm volatile("mbarrier.arrive.expect_tx.shared.b64 _, [%0], %1;"
                     :: "r"(mb0), "r"(EXG_BYTES) : "memory");
    }
    __syncthreads();
    // Barriers + zeroed h must be cluster-visible before any peer st.async.
    asm volatile("barrier.cluster.arrive.aligned;" ::: "memory");
    asm volatile("barrier.cluster.wait.aligned;" ::: "memory");

    // epilogue role (t < 128)
    const int rb = t >> 6;
    const int rj = t & 63;
    const int jg = (rank << 6) + rj;
    const long long bG_r = (long long)pair * 2 + rb;
    float bh0 = 0.f, bh1 = 0.f, bh2 = 0.f;
    const float* xp_base = xg;
    if (t < 128) {
        bh0 = bhh[jg];
        bh1 = bhh[256 + jg];
        bh2 = bhh[512 + jg];
        xp_base = xg + (bG_r << 10) * 768;
    }

    float2* const pp = reinterpret_cast<float2*>(pr + kh * 384 + 6 * lane);
    uint32_t ph0 = 0, ph1 = 0;  // wait parities per buffer

    for (int s = 0; s < PS; s++) {
        const int cur = s & 1, nxt = cur ^ 1;

        // prefetch xg (independent of h exchange; issue before the wait)
        float xr = 0.f, xz = 0.f, xn = 0.f;
        if (t < 128) {
            const float* xp = xp_base + (size_t)s * 768;
            xr = xp[jg];
            xz = xp[256 + jg];
            xn = xp[512 + jg];
        }

        // Wait for exchange s (h(s) bytes in buffer cur), then re-arm for s+2.
        if (s > 0) {
            if (cur) { mb_wait(mb1, ph1); ph1 ^= 1; }
            else     { mb_wait(mb0, ph0); ph0 ^= 1; }
            if (t == 0) {
                uint32_t mbc = cur ? mb1 : mb0;
                asm volatile("mbarrier.arrive.expect_tx.shared.b64 _, [%0], %1;"
                             :: "r"(mbc), "r"(EXG_BYTES) : "memory");
            }
        }

        float hp = 0.f;
        if (t < 128) hp = sh[(cur * 2 + rb) * 256 + jg];

        // --- matvec: both batches, weights from regs, h broadcast LDS.128 ---
#pragma unroll
        for (int b = 0; b < 2; b++) {
            ull a0 = 0ull, a1 = 0ull, a2 = 0ull;
            const float4* h4 = reinterpret_cast<const float4*>(sh + (cur * 2 + b) * 256 + kh * 32);
#pragma unroll
            for (int k4 = 0; k4 < 8; k4++) {
                float4 hv = h4[k4];
                ull hd;
                hd = dup2(hv.x);
                fma2(a0, w[0][k4 * 4 + 0], hd); fma2(a1, w[1][k4 * 4 + 0], hd); fma2(a2, w[2][k4 * 4 + 0], hd);
                hd = dup2(hv.y);
                fma2(a0, w[0][k4 * 4 + 1], hd); fma2(a1, w[1][k4 * 4 + 1], hd); fma2(a2, w[2][k4 * 4 + 1], hd);
                hd = dup2(hv.z);
                fma2(a0, w[0][k4 * 4 + 2], hd); fma2(a1, w[1][k4 * 4 + 2], hd); fma2(a2, w[2][k4 * 4 + 2], hd);
                hd = dup2(hv.w);
                fma2(a0, w[0][k4 * 4 + 3], hd); fma2(a1, w[1][k4 * 4 + 3], hd); fma2(a2, w[2][k4 * 4 + 3], hd);
            }
            float2* pb = pp + b * 96;
            pb[0] = unpack2(a0);
            pb[1] = unpack2(a1);
            pb[2] = unpack2(a2);
        }
        __syncthreads();

        // --- reduce + gates; publish h(s+1) via st.async to all 4 ranks ---
        if (t < 128) {
            float h0 = bh0, h1 = bh1, h2 = bh2;
#pragma unroll
            for (int q = 0; q < 8; q++) {
                const float* pq = pr + (q * 2 + rb) * 192;
                h0 += pq[rj];
                h1 += pq[64 + rj];
                h2 += pq[128 + rj];
            }
            float r = 0.5f + 0.5f * tanh_ap(0.5f * (xr + h0));
            float z = 0.5f + 0.5f * tanh_ap(0.5f * (xz + h1));
            float n = tanh_ap(xn + r * h2);
            float hn = (1.f - z) * n + z * hp;

            if (s < PS - 1) {
                uint32_t la  = shbase + (uint32_t)(((nxt * 2 + rb) * 256 + jg) * 4);
                uint32_t lmb = nxt ? mb1 : mb0;
#pragma unroll
                for (int rr = 0; rr < 4; rr++)
                    st_async_f32(la, lmb, (uint32_t)rr, hn);
            }
            long long row = (bG_r << 10) + s;
            dA[row * sA + oA + jg] = hn;
            dB[row * sB + oB + jg] = hn;
        }
        __syncthreads();   // WAR guard: pr reads done before next matvec writes
    }

    // Exit safety: no CTA leaves while peers could still touch its SMEM.
    asm volatile("barrier.cluster.arrive.aligned;" ::: "memory");
    asm volatile("barrier.cluster.wait.aligned;" ::: "memory");
}

// ---------------------------------------------------------------------------
extern "C" void kernel_launch(void* const* d_in, const int* in_sizes, int n_in,
                              void* d_out, int out_size) {
    const float* inp   = (const float*)d_in[0];
    const float* W_ih0 = (const float*)d_in[1];
    const float* W_hh0 = (const float*)d_in[2];
    const float* b_ih0 = (const float*)d_in[3];
    const float* b_hh0 = (const float*)d_in[4];
    const float* W_ih1 = (const float*)d_in[5];
    const float* W_hh1 = (const float*)d_in[6];
    const float* b_ih1 = (const float*)d_in[7];
    const float* b_hh1 = (const float*)d_in[8];
    float* out = (float*)d_out;

    float *xgp = nullptr, *h1p = nullptr;
    cudaGetSymbolAddress((void**)&xgp, g_xg);
    cudaGetSymbolAddress((void**)&h1p, g_h1);

    dim3 ggrid(12, 512);

    // Layer 0
    gemm_xg<<<ggrid, 256>>>(inp, W_ih0, b_ih0, xgp);
    gru_rec<<<128, 256>>>(xgp, W_hh0, b_hh0,
                          h1p, 256, 0,
                          out + BSH, 512, 0);
    // Layer 1
    gemm_xg<<<ggrid, 256>>>(h1p, W_ih1, b_ih1, xgp);
    gru_rec<<<128, 256>>>(xgp, W_hh1, b_hh1,
                          out, 256, 0,
                          out + BSH, 512, 256);
}